// round 6
// baseline (speedup 1.0000x reference)
#include <cuda_runtime.h>
#include <cstdint>

// ---------------------------------------------------------------------------
// VLLMFP8KVCache — confirmed harness dtype model (ALL non-int tensors = f32):
//   input        : f32   [8192, 1024]    (bf16-valued; 8,388,608 elems)
//   cache        : f32   [262144, 1024]  (e4m3-valued; 268,435,456 elems)
//   slot_mapping : int32 [8192]  (unique)
//   blocks       : int32 [32768]
//   d_out        : f32   [32768, 1024]
//
// Kernel 1: quantize f32 -> e4m3 (RNE satfinite, == ml_dtypes) -> exact f32,
//           scatter rows into cache in place (unique slots -> idempotent).
// Kernel 2: gather 4KB f32 rows into d_out (pure memcpy gather; e4m3 values
//           are exact in bf16, so the reference's bf16 round-trip is a no-op).
// ---------------------------------------------------------------------------

// two f32 -> exact e4m3-quantized f32 values (fast-math immune, RNE).
__device__ __forceinline__ void quant2(float a, float b, float& qa, float& qb)
{
    uint16_t r8;   // high byte <- b, low byte <- a
    asm("cvt.rn.satfinite.e4m3x2.f32 %0, %1, %2;" : "=h"(r8) : "f"(b), "f"(a));
    uint32_t h;    // two f16 holding the exact e4m3 values (low f16 <- low byte)
    asm("cvt.rn.f16x2.e4m3x2 %0, %1;" : "=r"(h) : "h"(r8));
    asm("{\n\t.reg .b16 x, y;\n\t"
        "mov.b32 {x, y}, %2;\n\t"
        "cvt.f32.f16 %0, x;\n\t"
        "cvt.f32.f16 %1, y;\n\t}"
        : "=f"(qa), "=f"(qb) : "r"(h));
}

// ---------------------------------------------------------------------------
// Kernel 1: scatter + quantize. 128 threads per 1024-elem row, 8 elems/thread
// (2 x 16B f32 loads -> 2 x 16B f32 stores).
// ---------------------------------------------------------------------------
__global__ void __launch_bounds__(256)
k_scatter_quant(const float* __restrict__ in,
                float* __restrict__ cache,
                const int* __restrict__ slots)
{
    int gid   = blockIdx.x * blockDim.x + threadIdx.x;
    int token = gid >> 7;                  // /128
    int j     = (gid & 127) << 3;          // elem offset in row

    int slot = __ldg(slots + token);

    const float4* src = reinterpret_cast<const float4*>(in + ((size_t)token << 10) + j);
    float4 v0 = src[0];
    float4 v1 = src[1];

    float4 q0, q1;
    quant2(v0.x, v0.y, q0.x, q0.y);
    quant2(v0.z, v0.w, q0.z, q0.w);
    quant2(v1.x, v1.y, q1.x, q1.y);
    quant2(v1.z, v1.w, q1.z, q1.w);

    float4* dst = reinterpret_cast<float4*>(cache + ((size_t)slot << 10) + j);
    dst[0] = q0;
    dst[1] = q1;
}

// ---------------------------------------------------------------------------
// Kernel 2: pure row gather (4KB f32 rows). 64 threads per row,
// 4 x 16B loads front-batched (MLP=4), 64B stored per thread.
// ---------------------------------------------------------------------------
__global__ void __launch_bounds__(256)
k_gather_rows(const float* __restrict__ cache,
              const int* __restrict__ blocks,
              float* __restrict__ out)
{
    int gid = blockIdx.x * blockDim.x + threadIdx.x;
    int row = gid >> 6;                    // /64
    int j   = (gid & 63) << 4;             // 16 elems/thread

    int b = __ldg(blocks + row);

    const uint4* src = reinterpret_cast<const uint4*>(cache + ((size_t)b << 10) + j);
    uint4 v0 = src[0];
    uint4 v1 = src[1];
    uint4 v2 = src[2];
    uint4 v3 = src[3];

    uint4* dst = reinterpret_cast<uint4*>(out + ((size_t)row << 10) + j);
    dst[0] = v0;
    dst[1] = v1;
    dst[2] = v2;
    dst[3] = v3;
}

// ---------------------------------------------------------------------------
extern "C" void kernel_launch(void* const* d_in, const int* in_sizes, int n_in,
                              void* d_out, int out_size)
{
    // Identify inputs by element count (order-independent; counts distinct).
    const float* input  = nullptr;
    float*       cache  = nullptr;
    const int*   slots  = nullptr;
    const int*   blocks = nullptr;
    int num_tokens = 8192, num_fetch = 32768;

    for (int i = 0; i < n_in; i++) {
        long long n = in_sizes[i];
        if      (n == 8388608LL)   input  = (const float*)d_in[i];
        else if (n == 268435456LL) cache  = (float*)d_in[i];
        else if (n == 8192LL)      slots  = (const int*)d_in[i];
        else if (n == 32768LL)     blocks = (const int*)d_in[i];
    }

    float* out = (float*)d_out;

    // 1) Scatter + quantize (in place; unique slots -> idempotent).
    {
        long long total = (long long)num_tokens * 128;   // threads
        int grid = (int)((total + 255) / 256);
        k_scatter_quant<<<grid, 256>>>(input, cache, slots);
    }

    // 2) Gather rows.
    {
        long long total = (long long)num_fetch * 64;     // threads
        int grid = (int)((total + 255) / 256);
        k_gather_rows<<<grid, 256>>>(cache, blocks, out);
    }
}

// round 9
// speedup vs baseline: 1.0584x; 1.0584x over previous
#include <cuda_runtime.h>
#include <cstdint>

// ---------------------------------------------------------------------------
// VLLMFP8KVCache — confirmed harness dtype model (ALL non-int tensors = f32):
//   input        : f32   [8192, 1024]    (bf16-valued)
//   cache        : f32   [262144, 1024]  (e4m3-valued; rows = 4KB)
//   slot_mapping : int32 [8192] (unique)   blocks : int32 [32768]
//   d_out        : f32   [32768, 1024]
//
// Kernel 1: quantize f32 -> e4m3 (RNE satfinite) -> exact f32, scatter rows
//           into cache in place (unique slots -> idempotent -> graph-safe).
// Kernel 2: TMA bulk-copy row gather: global->smem->global, 4KB rows,
//           8-stage pipeline, lookahead 4. Bypasses L1tex/regs entirely.
// ---------------------------------------------------------------------------

__device__ __forceinline__ uint32_t smem_u32(const void* p) {
    uint32_t a;
    asm("{ .reg .u64 t; cvta.to.shared.u64 t, %1; cvt.u32.u64 %0, t; }"
        : "=r"(a) : "l"(p));
    return a;
}

// two f32 -> exact e4m3-quantized f32 values (fast-math immune, RNE).
__device__ __forceinline__ void quant2(float a, float b, float& qa, float& qb)
{
    uint16_t r8;
    asm("cvt.rn.satfinite.e4m3x2.f32 %0, %1, %2;" : "=h"(r8) : "f"(b), "f"(a));
    uint32_t h;
    asm("cvt.rn.f16x2.e4m3x2 %0, %1;" : "=r"(h) : "h"(r8));
    asm("{\n\t.reg .b16 x, y;\n\t"
        "mov.b32 {x, y}, %2;\n\t"
        "cvt.f32.f16 %0, x;\n\t"
        "cvt.f32.f16 %1, y;\n\t}"
        : "=f"(qa), "=f"(qb) : "r"(h));
}

// ---------------------------------------------------------------------------
// Kernel 1: scatter + quantize. 128 threads/row, 8 elems/thread.
// ---------------------------------------------------------------------------
__global__ void __launch_bounds__(256)
k_scatter_quant(const float* __restrict__ in,
                float* __restrict__ cache,
                const int* __restrict__ slots)
{
    int gid   = blockIdx.x * blockDim.x + threadIdx.x;
    int token = gid >> 7;
    int j     = (gid & 127) << 3;

    int slot = __ldg(slots + token);

    const float4* src = reinterpret_cast<const float4*>(in + ((size_t)token << 10) + j);
    float4 v0 = src[0];
    float4 v1 = src[1];

    float4 q0, q1;
    quant2(v0.x, v0.y, q0.x, q0.y);
    quant2(v0.z, v0.w, q0.z, q0.w);
    quant2(v1.x, v1.y, q1.x, q1.y);
    quant2(v1.z, v1.w, q1.z, q1.w);

    float4* dst = reinterpret_cast<float4*>(cache + ((size_t)slot << 10) + j);
    dst[0] = q0;
    dst[1] = q1;
}

// ---------------------------------------------------------------------------
// Kernel 2: TMA bulk row gather.
//   8 x 4KB smem stages, load lookahead 4.
//   Stage s serves rows s (parity 0) and s+8 (parity 1); the wait for row r
//   completes before the refill at iter r+4 re-arms that stage -> no phase
//   aliasing. Refill overwrites row r-4's buffer; its store is 4 commit
//   groups old and wait_group.read<3> has drained its SMEM read -> no race.
// ---------------------------------------------------------------------------
#define GSTAGES   8
#define GLOOK     4
#define ROW_BYTES 4096

__global__ void __launch_bounds__(32)
k_gather_tma(const float* __restrict__ cache,
             const int* __restrict__ blocks,
             float* __restrict__ out,
             int rows_per_cta)
{
    __shared__ alignas(128) uint8_t  buf[GSTAGES][ROW_BYTES];
    __shared__ alignas(8)   uint64_t mbar[GSTAGES];

    if (threadIdx.x != 0) return;

    const int row0 = blockIdx.x * rows_per_cta;
    const uint32_t sbuf = smem_u32(buf);
    const uint32_t sbar = smem_u32(mbar);

    #pragma unroll
    for (int s = 0; s < GSTAGES; s++)
        asm volatile("mbarrier.init.shared.b64 [%0], 1;" :: "r"(sbar + s * 8) : "memory");
    asm volatile("fence.proxy.async.shared::cta;" ::: "memory");

    // Prime GLOOK loads.
    #pragma unroll
    for (int i = 0; i < GLOOK; i++) {
        int b = __ldg(blocks + row0 + i);
        const char* src = (const char*)cache + (size_t)b * ROW_BYTES;
        uint32_t bar = sbar + (i & (GSTAGES - 1)) * 8;
        asm volatile("mbarrier.arrive.expect_tx.shared.b64 _, [%0], %1;"
                     :: "r"(bar), "n"(ROW_BYTES) : "memory");
        asm volatile("cp.async.bulk.shared::cta.global.mbarrier::complete_tx::bytes "
                     "[%0], [%1], %2, [%3];"
                     :: "r"(sbuf + (i & (GSTAGES - 1)) * ROW_BYTES), "l"(src),
                        "n"(ROW_BYTES), "r"(bar) : "memory");
    }

    for (int r = 0; r < rows_per_cta; r++) {
        int s = r & (GSTAGES - 1);
        uint32_t bar = sbar + s * 8;
        uint32_t parity = (uint32_t)(r >> 3) & 1u;   // GSTAGES = 8

        // Wait for the load of row r (HW-sleep try_wait with time hint).
        asm volatile("{\n\t.reg .pred P;\n\t"
                     "W%=:\n\t"
                     "mbarrier.try_wait.parity.shared.b64 P, [%0], %1, 0x989680;\n\t"
                     "@!P bra W%=;\n\t}"
                     :: "r"(bar), "r"(parity) : "memory");

        // Store row r: smem -> out.
        char* dst = (char*)out + (size_t)(row0 + r) * ROW_BYTES;
        asm volatile("cp.async.bulk.global.shared::cta.bulk_group [%0], [%1], %2;"
                     :: "l"(dst), "r"(sbuf + s * ROW_BYTES), "n"(ROW_BYTES) : "memory");
        asm volatile("cp.async.bulk.commit_group;" ::: "memory");

        // Refill stage for row r+GLOOK once the stage's old SMEM read drained.
        int nxt = r + GLOOK;
        if (nxt < rows_per_cta) {
            asm volatile("cp.async.bulk.wait_group.read %0;" :: "n"(GLOOK - 1) : "memory");
            int b = __ldg(blocks + row0 + nxt);
            const char* src = (const char*)cache + (size_t)b * ROW_BYTES;
            int ns = nxt & (GSTAGES - 1);
            uint32_t nbar = sbar + ns * 8;
            asm volatile("mbarrier.arrive.expect_tx.shared.b64 _, [%0], %1;"
                         :: "r"(nbar), "n"(ROW_BYTES) : "memory");
            asm volatile("cp.async.bulk.shared::cta.global.mbarrier::complete_tx::bytes "
                         "[%0], [%1], %2, [%3];"
                         :: "r"(sbuf + ns * ROW_BYTES), "l"(src),
                            "n"(ROW_BYTES), "r"(nbar) : "memory");
        }
    }

    // Drain all stores (writes visible) before CTA exit.
    asm volatile("cp.async.bulk.wait_group %0;" :: "n"(0) : "memory");
}

// ---------------------------------------------------------------------------
extern "C" void kernel_launch(void* const* d_in, const int* in_sizes, int n_in,
                              void* d_out, int out_size)
{
    const float* input  = nullptr;
    float*       cache  = nullptr;
    const int*   slots  = nullptr;
    const int*   blocks = nullptr;
    const int num_tokens = 8192, num_fetch = 32768;

    for (int i = 0; i < n_in; i++) {
        long long n = in_sizes[i];
        if      (n == 8388608LL)   input  = (const float*)d_in[i];
        else if (n == 268435456LL) cache  = (float*)d_in[i];
        else if (n == 8192LL)      slots  = (const int*)d_in[i];
        else if (n == 32768LL)     blocks = (const int*)d_in[i];
    }
    if (!input || !cache || !slots || !blocks) return;  // fail loudly (poisoned out)

    float* out = (float*)d_out;

    // 1) Scatter + quantize (in place; unique slots -> idempotent).
    {
        long long total = (long long)num_tokens * 128;
        int grid = (int)((total + 255) / 256);
        k_scatter_quant<<<grid, 256>>>(input, cache, slots);
    }

    // 2) TMA bulk row gather: 2048 CTAs x 16 rows.
    {
        int rows_per_cta = 16;
        int grid = num_fetch / rows_per_cta;   // 2048
        k_gather_tma<<<grid, 32>>>(cache, blocks, out, rows_per_cta);
    }
}